// round 14
// baseline (speedup 1.0000x reference)
#include <cuda_runtime.h>
#include <math.h>

#define Bb   4
#define Ll   1024
#define Dd   1024
#define Hh   16
#define DHh  64
#define BH   64        // B*H
#define NTOK 4096      // B*L

// ---- scratch (device globals; no allocation in kernel_launch) ----
__device__ float g_q[BH * Ll * DHh];          // [bh, l, dh]  16 MB
__device__ float g_k[BH * Ll * DHh];          // 16 MB
__device__ float g_v[BH * Ll * DHh];          // 16 MB
__device__ float g_logits[67108864];          // [bh, q, k]  256 MB
__device__ float g_ctx[NTOK * Dd];            // [n, h*DH+dh] 16 MB

// ============================================================
// Generic NT GEMM: C[m,n] = scale * (sum_k A[m,k]*B[n,k] + bias[n])
// BM=BN=128, BK=8, 256 threads, 8x8 per thread. Batched via blockIdx.z.
// split==1: m is token (b,l), n is (h,dh) -> write [bh, l, dh] layout.
// ============================================================
__global__ void __launch_bounds__(256) sgemm_nt_kernel(
    const float* __restrict__ A, const float* __restrict__ Bw,
    const float* __restrict__ bias, float* __restrict__ C,
    int K, long long sA, long long sB, long long sC,
    float scale, int split)
{
    __shared__ float As[8][128];
    __shared__ float Bs[8][128];
    const int tid = threadIdx.x;
    const int z = blockIdx.z;
    A  += (long long)z * sA;
    Bw += (long long)z * sB;
    C  += (long long)z * sC;
    const int m0 = blockIdx.y * 128, n0 = blockIdx.x * 128;
    const int lr = tid >> 1, lk = (tid & 1) * 4;
    const float* Ap = A  + (long long)(m0 + lr) * K + lk;
    const float* Bp = Bw + (long long)(n0 + lr) * K + lk;
    const int ty = tid >> 4, tx = tid & 15;

    float acc[8][8];
#pragma unroll
    for (int i = 0; i < 8; i++)
#pragma unroll
        for (int j = 0; j < 8; j++) acc[i][j] = 0.f;

    for (int k0 = 0; k0 < K; k0 += 8) {
        float4 a = *(const float4*)(Ap + k0);
        float4 b = *(const float4*)(Bp + k0);
        __syncthreads();
        As[lk + 0][lr] = a.x; As[lk + 1][lr] = a.y;
        As[lk + 2][lr] = a.z; As[lk + 3][lr] = a.w;
        Bs[lk + 0][lr] = b.x; Bs[lk + 1][lr] = b.y;
        Bs[lk + 2][lr] = b.z; Bs[lk + 3][lr] = b.w;
        __syncthreads();
#pragma unroll
        for (int kk = 0; kk < 8; kk++) {
            float ar[8], br[8];
            *(float4*)(ar)     = *(const float4*)(&As[kk][ty * 8]);
            *(float4*)(ar + 4) = *(const float4*)(&As[kk][ty * 8 + 4]);
            *(float4*)(br)     = *(const float4*)(&Bs[kk][tx * 8]);
            *(float4*)(br + 4) = *(const float4*)(&Bs[kk][tx * 8 + 4]);
#pragma unroll
            for (int i = 0; i < 8; i++)
#pragma unroll
                for (int j = 0; j < 8; j++)
                    acc[i][j] += ar[i] * br[j];
        }
    }

#pragma unroll
    for (int i = 0; i < 8; i++) {
        const int m = m0 + ty * 8 + i;
        float v[8];
#pragma unroll
        for (int j = 0; j < 8; j++) {
            const int n = n0 + tx * 8 + j;
            float t = acc[i][j];
            if (bias) t += bias[n];
            v[j] = t * scale;
        }
        const int nbase = n0 + tx * 8;
        float* dst;
        if (split) {
            const int b = m >> 10, l = m & 1023;
            const int h = nbase >> 6, dh = nbase & 63;   // 8-wide stays in one head
            dst = C + ((long long)(b * Hh + h) * Ll + l) * DHh + dh;
        } else {
            dst = C + (long long)m * 1024 + nbase;
        }
        *(float4*)(dst)     = make_float4(v[0], v[1], v[2], v[3]);
        *(float4*)(dst + 4) = make_float4(v[4], v[5], v[6], v[7]);
    }
}

// ============================================================
// QR: logits[bh, q, k] += sum_d q[bh,q,d] * rel_k[q,k,d]
// One CTA per (q, k-tile of 128). rel_k read exactly once from DRAM.
// ============================================================
__global__ void __launch_bounds__(256) qr_add_kernel(
    const float* __restrict__ qv, const float* __restrict__ relk,
    float* __restrict__ logits)
{
    __shared__ float As[8][64];    // [d'][bh]
    __shared__ float Bs[8][128];   // [d'][k]
    const int tid = threadIdx.x;
    const int qp  = blockIdx.y;
    const int k0g = blockIdx.x * 128;
    const int lr = tid >> 1, lk = (tid & 1) * 4;
    const int ty = tid >> 4, tx = tid & 15;

    float acc[4][8];
#pragma unroll
    for (int i = 0; i < 4; i++)
#pragma unroll
        for (int j = 0; j < 8; j++) acc[i][j] = 0.f;

    const float* Ap = qv   + ((long long)lr * Ll + qp) * DHh + lk;        // lr = bh (tid<128)
    const float* Bp = relk + ((long long)qp * Ll + k0g + lr) * DHh + lk;  // lr = k row

    for (int d0 = 0; d0 < 64; d0 += 8) {
        float4 a = make_float4(0.f, 0.f, 0.f, 0.f);
        if (tid < 128) a = *(const float4*)(Ap + d0);
        float4 b = *(const float4*)(Bp + d0);
        __syncthreads();
        if (tid < 128) {
            As[lk + 0][lr] = a.x; As[lk + 1][lr] = a.y;
            As[lk + 2][lr] = a.z; As[lk + 3][lr] = a.w;
        }
        Bs[lk + 0][lr] = b.x; Bs[lk + 1][lr] = b.y;
        Bs[lk + 2][lr] = b.z; Bs[lk + 3][lr] = b.w;
        __syncthreads();
#pragma unroll
        for (int kk = 0; kk < 8; kk++) {
            float ar[4], br[8];
            *(float4*)(ar)     = *(const float4*)(&As[kk][ty * 4]);
            *(float4*)(br)     = *(const float4*)(&Bs[kk][tx * 8]);
            *(float4*)(br + 4) = *(const float4*)(&Bs[kk][tx * 8 + 4]);
#pragma unroll
            for (int i = 0; i < 4; i++)
#pragma unroll
                for (int j = 0; j < 8; j++)
                    acc[i][j] += ar[i] * br[j];
        }
    }

#pragma unroll
    for (int i = 0; i < 4; i++) {
        const int bh = ty * 4 + i;
        float* Cp = logits + ((long long)bh * Ll + qp) * Ll + k0g + tx * 8;
        float4 c0 = *(float4*)(Cp);
        float4 c1 = *(float4*)(Cp + 4);
        c0.x += acc[i][0]; c0.y += acc[i][1]; c0.z += acc[i][2]; c0.w += acc[i][3];
        c1.x += acc[i][4]; c1.y += acc[i][5]; c1.z += acc[i][6]; c1.w += acc[i][7];
        *(float4*)(Cp)     = c0;
        *(float4*)(Cp + 4) = c1;
    }
}

// ============================================================
// Row softmax with mask (in place). One CTA per (q, bh), 256 thr x 4 elems.
// ============================================================
__global__ void __launch_bounds__(256) softmax_kernel(
    float* __restrict__ logits, const unsigned char* __restrict__ mask)
{
    const int qp = blockIdx.x, bh = blockIdx.y;
    const int b = bh >> 4;
    float* row = logits + ((long long)bh * Ll + qp) * Ll;
    const unsigned char* mrow = mask + ((long long)b * Ll + qp) * Ll;
    const int tid = threadIdx.x;

    float4 xv = *(const float4*)(row + tid * 4);
    uchar4 mv = *(const uchar4*)(mrow + tid * 4);
    float x[4];
    x[0] = mv.x ? -10000.f : xv.x;
    x[1] = mv.y ? -10000.f : xv.y;
    x[2] = mv.z ? -10000.f : xv.z;
    x[3] = mv.w ? -10000.f : xv.w;

    __shared__ float smax[8], ssum[8], sbc[2];

    float lm = fmaxf(fmaxf(x[0], x[1]), fmaxf(x[2], x[3]));
#pragma unroll
    for (int o = 16; o; o >>= 1) lm = fmaxf(lm, __shfl_xor_sync(0xffffffffu, lm, o));
    if ((tid & 31) == 0) smax[tid >> 5] = lm;
    __syncthreads();
    if (tid == 0) {
        float v = smax[0];
#pragma unroll
        for (int w = 1; w < 8; w++) v = fmaxf(v, smax[w]);
        sbc[0] = v;
    }
    __syncthreads();
    const float bm = sbc[0];

    float e[4], s;
    e[0] = expf(x[0] - bm); e[1] = expf(x[1] - bm);
    e[2] = expf(x[2] - bm); e[3] = expf(x[3] - bm);
    s = (e[0] + e[1]) + (e[2] + e[3]);
#pragma unroll
    for (int o = 16; o; o >>= 1) s += __shfl_xor_sync(0xffffffffu, s, o);
    if ((tid & 31) == 0) ssum[tid >> 5] = s;
    __syncthreads();
    if (tid == 0) {
        float v = 0.f;
#pragma unroll
        for (int w = 0; w < 8; w++) v += ssum[w];
        sbc[1] = v;
    }
    __syncthreads();
    const float inv = 1.f / sbc[1];

    *(float4*)(row + tid * 4) = make_float4(e[0] * inv, e[1] * inv, e[2] * inv, e[3] * inv);
}

// ============================================================
// AV: ctx[b*L+q, h*64+d] = sum_k alpha[bh,q,k] * v[bh,k,d]
// One CTA per (bh, q-tile of 128). NN GEMM, BK=8, 8x4 per thread.
// ============================================================
__global__ void __launch_bounds__(256) av_kernel(
    const float* __restrict__ alpha, const float* __restrict__ vv,
    float* __restrict__ ctx)
{
    __shared__ float As[8][128];   // [k'][q]
    __shared__ float Vs[8][64];    // [k'][d]
    const int bh = blockIdx.y;
    const int q0 = blockIdx.x * 128;
    const int tid = threadIdx.x;
    const float* Ab = alpha + (long long)bh * Ll * Ll;
    const float* Vb = vv    + (long long)bh * Ll * DHh;
    const int lr = tid >> 1, lk = (tid & 1) * 4;    // alpha loads
    const int vr = tid >> 4, vc = (tid & 15) * 4;   // v loads (tid<128)
    const int ty = tid >> 4, tx = tid & 15;

    float acc[8][4];
#pragma unroll
    for (int i = 0; i < 8; i++)
#pragma unroll
        for (int j = 0; j < 4; j++) acc[i][j] = 0.f;

    const float* Ap = Ab + (long long)(q0 + lr) * Ll + lk;

    for (int k0 = 0; k0 < Ll; k0 += 8) {
        float4 a = *(const float4*)(Ap + k0);
        float4 v4 = make_float4(0.f, 0.f, 0.f, 0.f);
        if (tid < 128) v4 = *(const float4*)(Vb + (long long)(k0 + vr) * DHh + vc);
        __syncthreads();
        As[lk + 0][lr] = a.x; As[lk + 1][lr] = a.y;
        As[lk + 2][lr] = a.z; As[lk + 3][lr] = a.w;
        if (tid < 128) *(float4*)(&Vs[vr][vc]) = v4;
        __syncthreads();
#pragma unroll
        for (int kk = 0; kk < 8; kk++) {
            float ar[8], br[4];
            *(float4*)(ar)     = *(const float4*)(&As[kk][ty * 8]);
            *(float4*)(ar + 4) = *(const float4*)(&As[kk][ty * 8 + 4]);
            *(float4*)(br)     = *(const float4*)(&Vs[kk][tx * 4]);
#pragma unroll
            for (int i = 0; i < 8; i++)
#pragma unroll
                for (int j = 0; j < 4; j++)
                    acc[i][j] += ar[i] * br[j];
        }
    }

    const int b = bh >> 4, h = bh & 15;
#pragma unroll
    for (int i = 0; i < 8; i++) {
        const int qq = q0 + ty * 8 + i;
        *(float4*)(ctx + (long long)(b * Ll + qq) * Dd + h * DHh + tx * 4)
            = make_float4(acc[i][0], acc[i][1], acc[i][2], acc[i][3]);
    }
}

// ============================================================
// AR: ctx[b*L+q, h*64+d] += sum_k alpha[bh,q,k] * rel_v[q,k,d]
// One CTA per q. rel_v read exactly once from DRAM.
// ============================================================
__global__ void __launch_bounds__(256) ar_add_kernel(
    const float* __restrict__ alpha, const float* __restrict__ relv,
    float* __restrict__ ctx)
{
    __shared__ float As[8][64];   // [k'][bh]
    __shared__ float Rs[8][64];   // [k'][d]
    const int qp = blockIdx.x;
    const int tid = threadIdx.x;
    const int lr = tid >> 1, lk = (tid & 1) * 4;    // alpha: bh rows (tid<128)
    const int rr = tid >> 4, rc = (tid & 15) * 4;   // relv rows (tid<128)
    const int ty = tid >> 4, tx = tid & 15;

    float acc[4][4];
#pragma unroll
    for (int i = 0; i < 4; i++)
#pragma unroll
        for (int j = 0; j < 4; j++) acc[i][j] = 0.f;

    const float* Ap = alpha + ((long long)lr * Ll + qp) * Ll + lk;
    const float* Rp = relv + (long long)qp * Ll * DHh;

    for (int k0 = 0; k0 < Ll; k0 += 8) {
        float4 a = make_float4(0.f, 0.f, 0.f, 0.f);
        float4 r = make_float4(0.f, 0.f, 0.f, 0.f);
        if (tid < 128) {
            a = *(const float4*)(Ap + k0);
            r = *(const float4*)(Rp + (long long)(k0 + rr) * DHh + rc);
        }
        __syncthreads();
        if (tid < 128) {
            As[lk + 0][lr] = a.x; As[lk + 1][lr] = a.y;
            As[lk + 2][lr] = a.z; As[lk + 3][lr] = a.w;
            *(float4*)(&Rs[rr][rc]) = r;
        }
        __syncthreads();
#pragma unroll
        for (int kk = 0; kk < 8; kk++) {
            float4 ar4 = *(const float4*)(&As[kk][ty * 4]);
            float4 br4 = *(const float4*)(&Rs[kk][tx * 4]);
            const float ar[4] = {ar4.x, ar4.y, ar4.z, ar4.w};
            const float br[4] = {br4.x, br4.y, br4.z, br4.w};
#pragma unroll
            for (int i = 0; i < 4; i++)
#pragma unroll
                for (int j = 0; j < 4; j++)
                    acc[i][j] += ar[i] * br[j];
        }
    }

#pragma unroll
    for (int i = 0; i < 4; i++) {
        const int bh = ty * 4 + i;
        const int b = bh >> 4, h = bh & 15;
        float* Cp = ctx + (long long)(b * Ll + qp) * Dd + h * DHh + tx * 4;
        float4 c = *(float4*)Cp;
        c.x += acc[i][0]; c.y += acc[i][1]; c.z += acc[i][2]; c.w += acc[i][3];
        *(float4*)Cp = c;
    }
}

// ============================================================
extern "C" void kernel_launch(void* const* d_in, const int* in_sizes, int n_in,
                              void* d_out, int out_size)
{
    const float* key   = (const float*)d_in[0];
    const float* value = (const float*)d_in[1];
    const float* query = (const float*)d_in[2];
    const unsigned char* mask = (const unsigned char*)d_in[3];
    const float* rel_k = (const float*)d_in[4];
    const float* rel_v = (const float*)d_in[5];
    const float* Wk = (const float*)d_in[6];
    const float* bk = (const float*)d_in[7];
    const float* Wv = (const float*)d_in[8];
    const float* bv = (const float*)d_in[9];
    const float* Wq = (const float*)d_in[10];
    const float* bq = (const float*)d_in[11];
    const float* Wo = (const float*)d_in[12];
    const float* bo = (const float*)d_in[13];
    float* out = (float*)d_out;

    float *pq, *pk, *pv, *plog, *pctx;
    cudaGetSymbolAddress((void**)&pq,   g_q);
    cudaGetSymbolAddress((void**)&pk,   g_k);
    cudaGetSymbolAddress((void**)&pv,   g_v);
    cudaGetSymbolAddress((void**)&plog, g_logits);
    cudaGetSymbolAddress((void**)&pctx, g_ctx);

    dim3 blk(256);

    // Q/K/V projections: [4096,1024] x [1024,1024]^T, split-head output.
    sgemm_nt_kernel<<<dim3(8, 32, 1), blk>>>(query, Wq, bq, pq, 1024, 0, 0, 0, 0.125f, 1);
    sgemm_nt_kernel<<<dim3(8, 32, 1), blk>>>(key,   Wk, bk, pk, 1024, 0, 0, 0, 1.0f,   1);
    sgemm_nt_kernel<<<dim3(8, 32, 1), blk>>>(value, Wv, bv, pv, 1024, 0, 0, 0, 1.0f,   1);

    // QK logits: batched over bh, K=64.
    sgemm_nt_kernel<<<dim3(8, 8, 64), blk>>>(pq, pk, nullptr, plog, 64,
        (long long)Ll * DHh, (long long)Ll * DHh, (long long)Ll * Ll, 1.0f, 0);

    // += relative-key score (rel_k streamed once).
    qr_add_kernel<<<dim3(8, 1024), blk>>>(pq, rel_k, plog);

    // masked softmax in place.
    softmax_kernel<<<dim3(1024, 64), blk>>>(plog, mask);

    // alpha @ V -> ctx
    av_kernel<<<dim3(8, 64), blk>>>(plog, pv, pctx);

    // ctx += alpha @ rel_v (rel_v streamed once).
    ar_add_kernel<<<dim3(1024, 1, 1), blk>>>(plog, rel_v, pctx);

    // output projection.
    sgemm_nt_kernel<<<dim3(8, 32, 1), blk>>>(pctx, Wo, bo, out, 1024, 0, 0, 0, 1.0f, 0);
}

// round 15
// speedup vs baseline: 1.9683x; 1.9683x over previous
#include <cuda_runtime.h>
#include <math.h>

#define Bb   4
#define Ll   1024
#define Dd   1024
#define Hh   16
#define DHh  64
#define BH   64        // B*H
#define NTOK 4096      // B*L

// ---- scratch (device globals; no allocation in kernel_launch) ----
__device__ float g_q[BH * Ll * DHh];          // [bh, l, dh]  16 MB
__device__ float g_k[BH * Ll * DHh];          // 16 MB
__device__ float g_v[BH * Ll * DHh];          // 16 MB
__device__ float g_logits[67108864];          // [bh, q, k]  256 MB
__device__ float g_ctx[NTOK * Dd];            // [n, h*DH+dh] 16 MB

// ---- tf32 helpers -------------------------------------------------
__device__ __forceinline__ unsigned f2tf(float x) {
    unsigned r;
    asm("cvt.rna.tf32.f32 %0, %1;" : "=r"(r) : "f"(x));
    return r;
}

// D += A(16x8, row) * B(8x8, col).  tf32 in, fp32 accumulate.
// A frag: a0=(g, t) a1=(g+8, t) a2=(g, t+4) a3=(g+8, t+4)   [g=lane>>2, t=lane&3]
// B frag: b0=(k=t, n=g) b1=(k=t+4, n=g)
// C frag: c0=(g, 2t) c1=(g, 2t+1) c2=(g+8, 2t) c3=(g+8, 2t+1)
__device__ __forceinline__ void mma_tf32(float* c, const unsigned* a, const unsigned* b) {
    asm volatile(
        "mma.sync.aligned.m16n8k8.row.col.f32.tf32.tf32.f32 "
        "{%0,%1,%2,%3}, {%4,%5,%6,%7}, {%8,%9}, {%0,%1,%2,%3};\n"
        : "+f"(c[0]), "+f"(c[1]), "+f"(c[2]), "+f"(c[3])
        : "r"(a[0]), "r"(a[1]), "r"(a[2]), "r"(a[3]), "r"(b[0]), "r"(b[1]));
}

// ============================================================
// Generic NT GEMM (tensor core): C[m,n] = scale*(sum_k A[m,k]B[n,k] + bias[n])
// BM=BN=128, BK=16, 256 thr / 8 warps, warp tile 32x64.
// split==1: m=(b,l), n=(h,dh) -> write [bh,l,dh].
// ============================================================
__global__ void __launch_bounds__(256, 2) gemm_nt_tc(
    const float* __restrict__ A, const float* __restrict__ Bw,
    const float* __restrict__ bias, float* __restrict__ C,
    int K, long long sA, long long sB, long long sC,
    float scale, int split)
{
    __shared__ unsigned As[16][136];   // [k][m], stride 136 (%32==8 -> conflict-free frags)
    __shared__ unsigned Bs[16][136];   // [k][n]
    const int tid = threadIdx.x;
    const int z = blockIdx.z;
    A  += (long long)z * sA;
    Bw += (long long)z * sB;
    C  += (long long)z * sC;
    const int m0 = blockIdx.y * 128, n0 = blockIdx.x * 128;
    const int lr = tid >> 1, lk = (tid & 1) * 8;
    const float* Ap = A  + (long long)(m0 + lr) * K + lk;
    const float* Bp = Bw + (long long)(n0 + lr) * K + lk;
    const int w = tid >> 5, lane = tid & 31;
    const int wm = (w >> 1) * 32, wn = (w & 1) * 64;
    const int gid = lane >> 2, tig = lane & 3;

    float acc[2][8][4];
#pragma unroll
    for (int i = 0; i < 2; i++)
#pragma unroll
        for (int j = 0; j < 8; j++)
#pragma unroll
            for (int u = 0; u < 4; u++) acc[i][j][u] = 0.f;

    for (int k0 = 0; k0 < K; k0 += 16) {
        float4 a0 = *(const float4*)(Ap + k0);
        float4 a1 = *(const float4*)(Ap + k0 + 4);
        float4 b0 = *(const float4*)(Bp + k0);
        float4 b1 = *(const float4*)(Bp + k0 + 4);
        __syncthreads();
        As[lk + 0][lr] = f2tf(a0.x); As[lk + 1][lr] = f2tf(a0.y);
        As[lk + 2][lr] = f2tf(a0.z); As[lk + 3][lr] = f2tf(a0.w);
        As[lk + 4][lr] = f2tf(a1.x); As[lk + 5][lr] = f2tf(a1.y);
        As[lk + 6][lr] = f2tf(a1.z); As[lk + 7][lr] = f2tf(a1.w);
        Bs[lk + 0][lr] = f2tf(b0.x); Bs[lk + 1][lr] = f2tf(b0.y);
        Bs[lk + 2][lr] = f2tf(b0.z); Bs[lk + 3][lr] = f2tf(b0.w);
        Bs[lk + 4][lr] = f2tf(b1.x); Bs[lk + 5][lr] = f2tf(b1.y);
        Bs[lk + 6][lr] = f2tf(b1.z); Bs[lk + 7][lr] = f2tf(b1.w);
        __syncthreads();
#pragma unroll
        for (int kk = 0; kk < 16; kk += 8) {
            unsigned af[2][4];
#pragma unroll
            for (int mt = 0; mt < 2; mt++) {
                const int r = wm + mt * 16 + gid;
                af[mt][0] = As[kk + tig][r];
                af[mt][1] = As[kk + tig][r + 8];
                af[mt][2] = As[kk + tig + 4][r];
                af[mt][3] = As[kk + tig + 4][r + 8];
            }
#pragma unroll
            for (int nt = 0; nt < 8; nt++) {
                unsigned bf[2];
                const int c = wn + nt * 8 + gid;
                bf[0] = Bs[kk + tig][c];
                bf[1] = Bs[kk + tig + 4][c];
                mma_tf32(acc[0][nt], af[0], bf);
                mma_tf32(acc[1][nt], af[1], bf);
            }
        }
    }

#pragma unroll
    for (int mt = 0; mt < 2; mt++) {
#pragma unroll
        for (int half = 0; half < 2; half++) {
            const int r = m0 + wm + mt * 16 + gid + half * 8;
#pragma unroll
            for (int nt = 0; nt < 8; nt++) {
                const int col = n0 + wn + nt * 8 + 2 * tig;
                float x = acc[mt][nt][half * 2 + 0];
                float y = acc[mt][nt][half * 2 + 1];
                if (bias) { x += bias[col]; y += bias[col + 1]; }
                x *= scale; y *= scale;
                float* dst;
                if (split) {
                    const int b = r >> 10, l = r & 1023;
                    const int h = col >> 6, dh = col & 63;
                    dst = C + ((long long)(b * Hh + h) * Ll + l) * DHh + dh;
                } else {
                    dst = C + (long long)r * 1024 + col;
                }
                float2 v2; v2.x = x; v2.y = y;
                *(float2*)dst = v2;
            }
        }
    }
}

// ============================================================
// QR (tensor core): logits[bh,q,k] += sum_d q[bh,q,d] * rel_k[q,k,d]
// Per (q, k-tile 128): M=64(bh), N=128(k), K=64(d). rel_k streamed once.
// 8 warps, warp tile 32x32.
// ============================================================
__global__ void __launch_bounds__(256, 2) qr_tc(
    const float* __restrict__ qv, const float* __restrict__ relk,
    float* __restrict__ logits)
{
    __shared__ unsigned As[16][72];    // [d][bh]
    __shared__ unsigned Bs[16][136];   // [d][k]
    const int tid = threadIdx.x;
    const int qp = blockIdx.y, k0g = blockIdx.x * 128;
    const int w = tid >> 5, lane = tid & 31;
    const int gid = lane >> 2, tig = lane & 3;
    const int wm = (w >> 2) * 32, wn = (w & 3) * 32;
    const int arow = tid >> 2, ak = (tid & 3) * 4;
    const int brow = tid >> 1, bk = (tid & 1) * 8;
    const float* Ap = qv   + ((long long)arow * Ll + qp) * DHh + ak;
    const float* Bp = relk + ((long long)qp * Ll + k0g + brow) * DHh + bk;

    float acc[2][4][4];
#pragma unroll
    for (int i = 0; i < 2; i++)
#pragma unroll
        for (int j = 0; j < 4; j++)
#pragma unroll
            for (int u = 0; u < 4; u++) acc[i][j][u] = 0.f;

#pragma unroll
    for (int d0 = 0; d0 < 64; d0 += 16) {
        float4 a  = *(const float4*)(Ap + d0);
        float4 b0 = *(const float4*)(Bp + d0);
        float4 b1 = *(const float4*)(Bp + d0 + 4);
        __syncthreads();
        As[ak + 0][arow] = f2tf(a.x); As[ak + 1][arow] = f2tf(a.y);
        As[ak + 2][arow] = f2tf(a.z); As[ak + 3][arow] = f2tf(a.w);
        Bs[bk + 0][brow] = f2tf(b0.x); Bs[bk + 1][brow] = f2tf(b0.y);
        Bs[bk + 2][brow] = f2tf(b0.z); Bs[bk + 3][brow] = f2tf(b0.w);
        Bs[bk + 4][brow] = f2tf(b1.x); Bs[bk + 5][brow] = f2tf(b1.y);
        Bs[bk + 6][brow] = f2tf(b1.z); Bs[bk + 7][brow] = f2tf(b1.w);
        __syncthreads();
#pragma unroll
        for (int kk = 0; kk < 16; kk += 8) {
            unsigned af[2][4];
#pragma unroll
            for (int mt = 0; mt < 2; mt++) {
                const int r = wm + mt * 16 + gid;
                af[mt][0] = As[kk + tig][r];
                af[mt][1] = As[kk + tig][r + 8];
                af[mt][2] = As[kk + tig + 4][r];
                af[mt][3] = As[kk + tig + 4][r + 8];
            }
#pragma unroll
            for (int nt = 0; nt < 4; nt++) {
                unsigned bf[2];
                const int c = wn + nt * 8 + gid;
                bf[0] = Bs[kk + tig][c];
                bf[1] = Bs[kk + tig + 4][c];
                mma_tf32(acc[0][nt], af[0], bf);
                mma_tf32(acc[1][nt], af[1], bf);
            }
        }
    }

#pragma unroll
    for (int mt = 0; mt < 2; mt++) {
#pragma unroll
        for (int half = 0; half < 2; half++) {
            const int bh = wm + mt * 16 + gid + half * 8;
#pragma unroll
            for (int nt = 0; nt < 4; nt++) {
                const int col = k0g + wn + nt * 8 + 2 * tig;
                float* Cp = logits + ((long long)bh * Ll + qp) * Ll + col;
                float2 c = *(float2*)Cp;
                c.x += acc[mt][nt][half * 2 + 0];
                c.y += acc[mt][nt][half * 2 + 1];
                *(float2*)Cp = c;
            }
        }
    }
}

// ============================================================
// Row softmax with mask (in place). One CTA per (q, bh).
// ============================================================
__global__ void __launch_bounds__(256) softmax_kernel(
    float* __restrict__ logits, const unsigned char* __restrict__ mask)
{
    const int qp = blockIdx.x, bh = blockIdx.y;
    const int b = bh >> 4;
    float* row = logits + ((long long)bh * Ll + qp) * Ll;
    const unsigned char* mrow = mask + ((long long)b * Ll + qp) * Ll;
    const int tid = threadIdx.x;

    float4 xv = *(const float4*)(row + tid * 4);
    uchar4 mv = *(const uchar4*)(mrow + tid * 4);
    float x[4];
    x[0] = mv.x ? -10000.f : xv.x;
    x[1] = mv.y ? -10000.f : xv.y;
    x[2] = mv.z ? -10000.f : xv.z;
    x[3] = mv.w ? -10000.f : xv.w;

    __shared__ float smax[8], ssum[8], sbc[2];

    float lm = fmaxf(fmaxf(x[0], x[1]), fmaxf(x[2], x[3]));
#pragma unroll
    for (int o = 16; o; o >>= 1) lm = fmaxf(lm, __shfl_xor_sync(0xffffffffu, lm, o));
    if ((tid & 31) == 0) smax[tid >> 5] = lm;
    __syncthreads();
    if (tid == 0) {
        float v = smax[0];
#pragma unroll
        for (int ww = 1; ww < 8; ww++) v = fmaxf(v, smax[ww]);
        sbc[0] = v;
    }
    __syncthreads();
    const float bm = sbc[0];

    float e[4], s;
    e[0] = expf(x[0] - bm); e[1] = expf(x[1] - bm);
    e[2] = expf(x[2] - bm); e[3] = expf(x[3] - bm);
    s = (e[0] + e[1]) + (e[2] + e[3]);
#pragma unroll
    for (int o = 16; o; o >>= 1) s += __shfl_xor_sync(0xffffffffu, s, o);
    if ((tid & 31) == 0) ssum[tid >> 5] = s;
    __syncthreads();
    if (tid == 0) {
        float v = 0.f;
#pragma unroll
        for (int ww = 0; ww < 8; ww++) v += ssum[ww];
        sbc[1] = v;
    }
    __syncthreads();
    const float inv = 1.f / sbc[1];

    *(float4*)(row + tid * 4) = make_float4(e[0] * inv, e[1] * inv, e[2] * inv, e[3] * inv);
}

// ============================================================
// AV (tensor core, NN): ctx[b*L+q, h*64+d] = sum_k alpha[bh,q,k] v[bh,k,d]
// Per (bh, q-tile 128): M=128, N=64, K=1024. 8 warps, warp tile 32x32.
// ============================================================
__global__ void __launch_bounds__(256, 2) av_tc(
    const float* __restrict__ alpha, const float* __restrict__ vv,
    float* __restrict__ ctx)
{
    __shared__ unsigned As[16][136];   // [k][q]
    __shared__ unsigned Bs[16][72];    // [k][d]
    const int tid = threadIdx.x;
    const int bh = blockIdx.y, q0 = blockIdx.x * 128;
    const int w = tid >> 5, lane = tid & 31;
    const int gid = lane >> 2, tig = lane & 3;
    const int wm = (w >> 1) * 32, wn = (w & 1) * 32;
    const int arow = tid >> 1, ak = (tid & 1) * 8;
    const int vrow = tid >> 4, vcol = (tid & 15) * 4;
    const float* Ap = alpha + (long long)bh * Ll * Ll + (long long)(q0 + arow) * Ll + ak;
    const float* Vp = vv + (long long)bh * Ll * DHh + (long long)vrow * DHh + vcol;

    float acc[2][4][4];
#pragma unroll
    for (int i = 0; i < 2; i++)
#pragma unroll
        for (int j = 0; j < 4; j++)
#pragma unroll
            for (int u = 0; u < 4; u++) acc[i][j][u] = 0.f;

    for (int k0 = 0; k0 < Ll; k0 += 16) {
        float4 a0 = *(const float4*)(Ap + k0);
        float4 a1 = *(const float4*)(Ap + k0 + 4);
        float4 v4 = *(const float4*)(Vp + (long long)k0 * DHh);
        __syncthreads();
        As[ak + 0][arow] = f2tf(a0.x); As[ak + 1][arow] = f2tf(a0.y);
        As[ak + 2][arow] = f2tf(a0.z); As[ak + 3][arow] = f2tf(a0.w);
        As[ak + 4][arow] = f2tf(a1.x); As[ak + 5][arow] = f2tf(a1.y);
        As[ak + 6][arow] = f2tf(a1.z); As[ak + 7][arow] = f2tf(a1.w);
        uint4 t;
        t.x = f2tf(v4.x); t.y = f2tf(v4.y); t.z = f2tf(v4.z); t.w = f2tf(v4.w);
        *(uint4*)&Bs[vrow][vcol] = t;
        __syncthreads();
#pragma unroll
        for (int kk = 0; kk < 16; kk += 8) {
            unsigned af[2][4];
#pragma unroll
            for (int mt = 0; mt < 2; mt++) {
                const int r = wm + mt * 16 + gid;
                af[mt][0] = As[kk + tig][r];
                af[mt][1] = As[kk + tig][r + 8];
                af[mt][2] = As[kk + tig + 4][r];
                af[mt][3] = As[kk + tig + 4][r + 8];
            }
#pragma unroll
            for (int nt = 0; nt < 4; nt++) {
                unsigned bf[2];
                const int c = wn + nt * 8 + gid;
                bf[0] = Bs[kk + tig][c];
                bf[1] = Bs[kk + tig + 4][c];
                mma_tf32(acc[0][nt], af[0], bf);
                mma_tf32(acc[1][nt], af[1], bf);
            }
        }
    }

    const int b = bh >> 4, h = bh & 15;
#pragma unroll
    for (int mt = 0; mt < 2; mt++) {
#pragma unroll
        for (int half = 0; half < 2; half++) {
            const int q = q0 + wm + mt * 16 + gid + half * 8;
#pragma unroll
            for (int nt = 0; nt < 4; nt++) {
                const int d = wn + nt * 8 + 2 * tig;
                float2 v2;
                v2.x = acc[mt][nt][half * 2 + 0];
                v2.y = acc[mt][nt][half * 2 + 1];
                *(float2*)(ctx + ((long long)(b * Ll + q)) * Dd + h * DHh + d) = v2;
            }
        }
    }
}

// ============================================================
// AR (tensor core, NN): ctx[b*L+q, h*64+d] += sum_k alpha[bh,q,k] rel_v[q,k,d]
// Per q: M=64(bh), N=64(d), K=1024. rel_v streamed once. 8 warps, tile 16x32.
// ============================================================
__global__ void __launch_bounds__(256, 2) ar_tc(
    const float* __restrict__ alpha, const float* __restrict__ relv,
    float* __restrict__ ctx)
{
    __shared__ unsigned As[32][72];   // [k][bh]
    __shared__ unsigned Bs[32][72];   // [k][d]
    const int tid = threadIdx.x;
    const int qp = blockIdx.x;
    const int w = tid >> 5, lane = tid & 31;
    const int gid = lane >> 2, tig = lane & 3;
    const int wm = (w >> 1) * 16, wn = (w & 1) * 32;
    const int arow = tid >> 2, ak = (tid & 3) * 8;
    const int brow = tid >> 3, bc = (tid & 7) * 8;
    const float* Ap = alpha + ((long long)arow * Ll + qp) * Ll + ak;
    const float* Rp = relv + ((long long)qp * Ll + brow) * DHh + bc;

    float acc[4][4];
#pragma unroll
    for (int j = 0; j < 4; j++)
#pragma unroll
        for (int u = 0; u < 4; u++) acc[j][u] = 0.f;

    for (int k0 = 0; k0 < Ll; k0 += 32) {
        float4 a0 = *(const float4*)(Ap + k0);
        float4 a1 = *(const float4*)(Ap + k0 + 4);
        float4 r0 = *(const float4*)(Rp + (long long)k0 * DHh);
        float4 r1 = *(const float4*)(Rp + (long long)k0 * DHh + 4);
        __syncthreads();
        As[ak + 0][arow] = f2tf(a0.x); As[ak + 1][arow] = f2tf(a0.y);
        As[ak + 2][arow] = f2tf(a0.z); As[ak + 3][arow] = f2tf(a0.w);
        As[ak + 4][arow] = f2tf(a1.x); As[ak + 5][arow] = f2tf(a1.y);
        As[ak + 6][arow] = f2tf(a1.z); As[ak + 7][arow] = f2tf(a1.w);
        uint4 t0, t1;
        t0.x = f2tf(r0.x); t0.y = f2tf(r0.y); t0.z = f2tf(r0.z); t0.w = f2tf(r0.w);
        t1.x = f2tf(r1.x); t1.y = f2tf(r1.y); t1.z = f2tf(r1.z); t1.w = f2tf(r1.w);
        *(uint4*)&Bs[brow][bc]     = t0;
        *(uint4*)&Bs[brow][bc + 4] = t1;
        __syncthreads();
#pragma unroll
        for (int kk = 0; kk < 32; kk += 8) {
            unsigned af[4];
            const int r = wm + gid;
            af[0] = As[kk + tig][r];
            af[1] = As[kk + tig][r + 8];
            af[2] = As[kk + tig + 4][r];
            af[3] = As[kk + tig + 4][r + 8];
#pragma unroll
            for (int nt = 0; nt < 4; nt++) {
                unsigned bf[2];
                const int c = wn + nt * 8 + gid;
                bf[0] = Bs[kk + tig][c];
                bf[1] = Bs[kk + tig + 4][c];
                mma_tf32(acc[nt], af, bf);
            }
        }
    }

#pragma unroll
    for (int half = 0; half < 2; half++) {
        const int bh = wm + gid + half * 8;
        const int b = bh >> 4, h = bh & 15;
#pragma unroll
        for (int nt = 0; nt < 4; nt++) {
            const int d = wn + nt * 8 + 2 * tig;
            float* Cp = ctx + ((long long)(b * Ll + qp)) * Dd + h * DHh + d;
            float2 c = *(float2*)Cp;
            c.x += acc[nt][half * 2 + 0];
            c.y += acc[nt][half * 2 + 1];
            *(float2*)Cp = c;
        }
    }
}

// ============================================================
extern "C" void kernel_launch(void* const* d_in, const int* in_sizes, int n_in,
                              void* d_out, int out_size)
{
    const float* key   = (const float*)d_in[0];
    const float* value = (const float*)d_in[1];
    const float* query = (const float*)d_in[2];
    const unsigned char* mask = (const unsigned char*)d_in[3];
    const float* rel_k = (const float*)d_in[4];
    const float* rel_v = (const float*)d_in[5];
    const float* Wk = (const float*)d_in[6];
    const float* bk = (const float*)d_in[7];
    const float* Wv = (const float*)d_in[8];
    const float* bv = (const float*)d_in[9];
    const float* Wq = (const float*)d_in[10];
    const float* bq = (const float*)d_in[11];
    const float* Wo = (const float*)d_in[12];
    const float* bo = (const float*)d_in[13];
    float* out = (float*)d_out;

    float *pq, *pk, *pv, *plog, *pctx;
    cudaGetSymbolAddress((void**)&pq,   g_q);
    cudaGetSymbolAddress((void**)&pk,   g_k);
    cudaGetSymbolAddress((void**)&pv,   g_v);
    cudaGetSymbolAddress((void**)&plog, g_logits);
    cudaGetSymbolAddress((void**)&pctx, g_ctx);

    dim3 blk(256);

    // Q/K/V projections: [4096,1024] x [1024,1024]^T, split-head output.
    gemm_nt_tc<<<dim3(8, 32, 1), blk>>>(query, Wq, bq, pq, 1024, 0, 0, 0, 0.125f, 1);
    gemm_nt_tc<<<dim3(8, 32, 1), blk>>>(key,   Wk, bk, pk, 1024, 0, 0, 0, 1.0f,   1);
    gemm_nt_tc<<<dim3(8, 32, 1), blk>>>(value, Wv, bv, pv, 1024, 0, 0, 0, 1.0f,   1);

    // QK logits: batched over bh, K=64.
    gemm_nt_tc<<<dim3(8, 8, 64), blk>>>(pq, pk, nullptr, plog, 64,
        (long long)Ll * DHh, (long long)Ll * DHh, (long long)Ll * Ll, 1.0f, 0);

    // += relative-key score (rel_k streamed once).
    qr_tc<<<dim3(8, 1024), blk>>>(pq, rel_k, plog);

    // masked softmax in place.
    softmax_kernel<<<dim3(1024, 64), blk>>>(plog, mask);

    // alpha @ V -> ctx
    av_tc<<<dim3(8, 64), blk>>>(plog, pv, pctx);

    // ctx += alpha @ rel_v (rel_v streamed once).
    ar_tc<<<dim3(1024, 1, 1), blk>>>(plog, rel_v, pctx);

    // output projection.
    gemm_nt_tc<<<dim3(8, 32, 1), blk>>>(pctx, Wo, bo, out, 1024, 0, 0, 0, 1.0f, 0);
}

// round 16
// speedup vs baseline: 1.9698x; 1.0007x over previous
#include <cuda_runtime.h>
#include <math.h>

#define Bb   4
#define Ll   1024
#define Dd   1024
#define Hh   16
#define DHh  64
#define BH   64        // B*H
#define NTOK 4096      // B*L

// ---- scratch (device globals; no allocation in kernel_launch) ----
__device__ float g_q[BH * Ll * DHh];          // [bh, l, dh]  16 MB
__device__ float g_k[BH * Ll * DHh];          // 16 MB
__device__ float g_v[BH * Ll * DHh];          // 16 MB
__device__ float g_logits[67108864];          // [bh, q, k]  256 MB
__device__ float g_ctx[NTOK * Dd];            // [n, h*DH+dh] 16 MB

// ---- tf32 helpers -------------------------------------------------
__device__ __forceinline__ unsigned f2tf(float x) {
    unsigned r;
    asm("cvt.rna.tf32.f32 %0, %1;" : "=r"(r) : "f"(x));
    return r;
}

// D += A(16x8, row) * B(8x8, col).  tf32 in, fp32 accumulate.
// A frag: a0=(g, t) a1=(g+8, t) a2=(g, t+4) a3=(g+8, t+4)   [g=lane>>2, t=lane&3]
// B frag: b0=(k=t, n=g) b1=(k=t+4, n=g)
// C frag: c0=(g, 2t) c1=(g, 2t+1) c2=(g+8, 2t) c3=(g+8, 2t+1)
__device__ __forceinline__ void mma_tf32(float* c, const unsigned* a, const unsigned* b) {
    asm volatile(
        "mma.sync.aligned.m16n8k8.row.col.f32.tf32.tf32.f32 "
        "{%0,%1,%2,%3}, {%4,%5,%6,%7}, {%8,%9}, {%0,%1,%2,%3};\n"
        : "+f"(c[0]), "+f"(c[1]), "+f"(c[2]), "+f"(c[3])
        : "r"(a[0]), "r"(a[1]), "r"(a[2]), "r"(a[3]), "r"(b[0]), "r"(b[1]));
}

// ============================================================
// Generic NT GEMM (tensor core): C[m,n] = scale*(sum_k A[m,k]B[n,k] + bias[n])
// BM=BN=128, BK=16, 256 thr / 8 warps, warp tile 32x64.
// split==1: m=(b,l), n=(h,dh) -> write [bh,l,dh].
// ============================================================
__global__ void __launch_bounds__(256, 2) gemm_nt_tc(
    const float* __restrict__ A, const float* __restrict__ Bw,
    const float* __restrict__ bias, float* __restrict__ C,
    int K, long long sA, long long sB, long long sC,
    float scale, int split)
{
    __shared__ unsigned As[16][136];   // [k][m], stride 136 (%32==8 -> conflict-free frags)
    __shared__ unsigned Bs[16][136];   // [k][n]
    const int tid = threadIdx.x;
    const int z = blockIdx.z;
    A  += (long long)z * sA;
    Bw += (long long)z * sB;
    C  += (long long)z * sC;
    const int m0 = blockIdx.y * 128, n0 = blockIdx.x * 128;
    const int lr = tid >> 1, lk = (tid & 1) * 8;
    const float* Ap = A  + (long long)(m0 + lr) * K + lk;
    const float* Bp = Bw + (long long)(n0 + lr) * K + lk;
    const int w = tid >> 5, lane = tid & 31;
    const int wm = (w >> 1) * 32, wn = (w & 1) * 64;
    const int gid = lane >> 2, tig = lane & 3;

    float acc[2][8][4];
#pragma unroll
    for (int i = 0; i < 2; i++)
#pragma unroll
        for (int j = 0; j < 8; j++)
#pragma unroll
            for (int u = 0; u < 4; u++) acc[i][j][u] = 0.f;

    for (int k0 = 0; k0 < K; k0 += 16) {
        float4 a0 = *(const float4*)(Ap + k0);
        float4 a1 = *(const float4*)(Ap + k0 + 4);
        float4 b0 = *(const float4*)(Bp + k0);
        float4 b1 = *(const float4*)(Bp + k0 + 4);
        __syncthreads();
        As[lk + 0][lr] = f2tf(a0.x); As[lk + 1][lr] = f2tf(a0.y);
        As[lk + 2][lr] = f2tf(a0.z); As[lk + 3][lr] = f2tf(a0.w);
        As[lk + 4][lr] = f2tf(a1.x); As[lk + 5][lr] = f2tf(a1.y);
        As[lk + 6][lr] = f2tf(a1.z); As[lk + 7][lr] = f2tf(a1.w);
        Bs[lk + 0][lr] = f2tf(b0.x); Bs[lk + 1][lr] = f2tf(b0.y);
        Bs[lk + 2][lr] = f2tf(b0.z); Bs[lk + 3][lr] = f2tf(b0.w);
        Bs[lk + 4][lr] = f2tf(b1.x); Bs[lk + 5][lr] = f2tf(b1.y);
        Bs[lk + 6][lr] = f2tf(b1.z); Bs[lk + 7][lr] = f2tf(b1.w);
        __syncthreads();
#pragma unroll
        for (int kk = 0; kk < 16; kk += 8) {
            unsigned af[2][4];
#pragma unroll
            for (int mt = 0; mt < 2; mt++) {
                const int r = wm + mt * 16 + gid;
                af[mt][0] = As[kk + tig][r];
                af[mt][1] = As[kk + tig][r + 8];
                af[mt][2] = As[kk + tig + 4][r];
                af[mt][3] = As[kk + tig + 4][r + 8];
            }
#pragma unroll
            for (int nt = 0; nt < 8; nt++) {
                unsigned bf[2];
                const int c = wn + nt * 8 + gid;
                bf[0] = Bs[kk + tig][c];
                bf[1] = Bs[kk + tig + 4][c];
                mma_tf32(acc[0][nt], af[0], bf);
                mma_tf32(acc[1][nt], af[1], bf);
            }
        }
    }

#pragma unroll
    for (int mt = 0; mt < 2; mt++) {
#pragma unroll
        for (int half = 0; half < 2; half++) {
            const int r = m0 + wm + mt * 16 + gid + half * 8;
#pragma unroll
            for (int nt = 0; nt < 8; nt++) {
                const int col = n0 + wn + nt * 8 + 2 * tig;
                float x = acc[mt][nt][half * 2 + 0];
                float y = acc[mt][nt][half * 2 + 1];
                if (bias) { x += bias[col]; y += bias[col + 1]; }
                x *= scale; y *= scale;
                float* dst;
                if (split) {
                    const int b = r >> 10, l = r & 1023;
                    const int h = col >> 6, dh = col & 63;
                    dst = C + ((long long)(b * Hh + h) * Ll + l) * DHh + dh;
                } else {
                    dst = C + (long long)r * 1024 + col;
                }
                float2 v2; v2.x = x; v2.y = y;
                *(float2*)dst = v2;
            }
        }
    }
}

// ============================================================
// QR (tensor core): logits[bh,q,k] += sum_d q[bh,q,d] * rel_k[q,k,d]
// Per (q, k-tile 128): M=64(bh), N=128(k), K=64(d). rel_k streamed once.
// 8 warps, warp tile 32x32.
// ============================================================
__global__ void __launch_bounds__(256, 2) qr_tc(
    const float* __restrict__ qv, const float* __restrict__ relk,
    float* __restrict__ logits)
{
    __shared__ unsigned As[16][72];    // [d][bh]
    __shared__ unsigned Bs[16][136];   // [d][k]
    const int tid = threadIdx.x;
    const int qp = blockIdx.y, k0g = blockIdx.x * 128;
    const int w = tid >> 5, lane = tid & 31;
    const int gid = lane >> 2, tig = lane & 3;
    const int wm = (w >> 2) * 32, wn = (w & 3) * 32;
    const int arow = tid >> 2, ak = (tid & 3) * 4;
    const int brow = tid >> 1, bk = (tid & 1) * 8;
    const float* Ap = qv   + ((long long)arow * Ll + qp) * DHh + ak;
    const float* Bp = relk + ((long long)qp * Ll + k0g + brow) * DHh + bk;

    float acc[2][4][4];
#pragma unroll
    for (int i = 0; i < 2; i++)
#pragma unroll
        for (int j = 0; j < 4; j++)
#pragma unroll
            for (int u = 0; u < 4; u++) acc[i][j][u] = 0.f;

#pragma unroll
    for (int d0 = 0; d0 < 64; d0 += 16) {
        float4 a  = *(const float4*)(Ap + d0);
        float4 b0 = *(const float4*)(Bp + d0);
        float4 b1 = *(const float4*)(Bp + d0 + 4);
        __syncthreads();
        As[ak + 0][arow] = f2tf(a.x); As[ak + 1][arow] = f2tf(a.y);
        As[ak + 2][arow] = f2tf(a.z); As[ak + 3][arow] = f2tf(a.w);
        Bs[bk + 0][brow] = f2tf(b0.x); Bs[bk + 1][brow] = f2tf(b0.y);
        Bs[bk + 2][brow] = f2tf(b0.z); Bs[bk + 3][brow] = f2tf(b0.w);
        Bs[bk + 4][brow] = f2tf(b1.x); Bs[bk + 5][brow] = f2tf(b1.y);
        Bs[bk + 6][brow] = f2tf(b1.z); Bs[bk + 7][brow] = f2tf(b1.w);
        __syncthreads();
#pragma unroll
        for (int kk = 0; kk < 16; kk += 8) {
            unsigned af[2][4];
#pragma unroll
            for (int mt = 0; mt < 2; mt++) {
                const int r = wm + mt * 16 + gid;
                af[mt][0] = As[kk + tig][r];
                af[mt][1] = As[kk + tig][r + 8];
                af[mt][2] = As[kk + tig + 4][r];
                af[mt][3] = As[kk + tig + 4][r + 8];
            }
#pragma unroll
            for (int nt = 0; nt < 4; nt++) {
                unsigned bf[2];
                const int c = wn + nt * 8 + gid;
                bf[0] = Bs[kk + tig][c];
                bf[1] = Bs[kk + tig + 4][c];
                mma_tf32(acc[0][nt], af[0], bf);
                mma_tf32(acc[1][nt], af[1], bf);
            }
        }
    }

#pragma unroll
    for (int mt = 0; mt < 2; mt++) {
#pragma unroll
        for (int half = 0; half < 2; half++) {
            const int bh = wm + mt * 16 + gid + half * 8;
#pragma unroll
            for (int nt = 0; nt < 4; nt++) {
                const int col = k0g + wn + nt * 8 + 2 * tig;
                float* Cp = logits + ((long long)bh * Ll + qp) * Ll + col;
                float2 c = *(float2*)Cp;
                c.x += acc[mt][nt][half * 2 + 0];
                c.y += acc[mt][nt][half * 2 + 1];
                *(float2*)Cp = c;
            }
        }
    }
}

// ============================================================
// Row softmax with mask (in place). One CTA per (q, bh).
// ============================================================
__global__ void __launch_bounds__(256) softmax_kernel(
    float* __restrict__ logits, const unsigned char* __restrict__ mask)
{
    const int qp = blockIdx.x, bh = blockIdx.y;
    const int b = bh >> 4;
    float* row = logits + ((long long)bh * Ll + qp) * Ll;
    const unsigned char* mrow = mask + ((long long)b * Ll + qp) * Ll;
    const int tid = threadIdx.x;

    float4 xv = *(const float4*)(row + tid * 4);
    uchar4 mv = *(const uchar4*)(mrow + tid * 4);
    float x[4];
    x[0] = mv.x ? -10000.f : xv.x;
    x[1] = mv.y ? -10000.f : xv.y;
    x[2] = mv.z ? -10000.f : xv.z;
    x[3] = mv.w ? -10000.f : xv.w;

    __shared__ float smax[8], ssum[8], sbc[2];

    float lm = fmaxf(fmaxf(x[0], x[1]), fmaxf(x[2], x[3]));
#pragma unroll
    for (int o = 16; o; o >>= 1) lm = fmaxf(lm, __shfl_xor_sync(0xffffffffu, lm, o));
    if ((tid & 31) == 0) smax[tid >> 5] = lm;
    __syncthreads();
    if (tid == 0) {
        float v = smax[0];
#pragma unroll
        for (int ww = 1; ww < 8; ww++) v = fmaxf(v, smax[ww]);
        sbc[0] = v;
    }
    __syncthreads();
    const float bm = sbc[0];

    float e[4], s;
    e[0] = expf(x[0] - bm); e[1] = expf(x[1] - bm);
    e[2] = expf(x[2] - bm); e[3] = expf(x[3] - bm);
    s = (e[0] + e[1]) + (e[2] + e[3]);
#pragma unroll
    for (int o = 16; o; o >>= 1) s += __shfl_xor_sync(0xffffffffu, s, o);
    if ((tid & 31) == 0) ssum[tid >> 5] = s;
    __syncthreads();
    if (tid == 0) {
        float v = 0.f;
#pragma unroll
        for (int ww = 0; ww < 8; ww++) v += ssum[ww];
        sbc[1] = v;
    }
    __syncthreads();
    const float inv = 1.f / sbc[1];

    *(float4*)(row + tid * 4) = make_float4(e[0] * inv, e[1] * inv, e[2] * inv, e[3] * inv);
}

// ============================================================
// AV (tensor core, NN): ctx[b*L+q, h*64+d] = sum_k alpha[bh,q,k] v[bh,k,d]
// Per (bh, q-tile 128): M=128, N=64, K=1024. 8 warps, warp tile 32x32.
// ============================================================
__global__ void __launch_bounds__(256, 2) av_tc(
    const float* __restrict__ alpha, const float* __restrict__ vv,
    float* __restrict__ ctx)
{
    __shared__ unsigned As[16][136];   // [k][q]
    __shared__ unsigned Bs[16][72];    // [k][d]
    const int tid = threadIdx.x;
    const int bh = blockIdx.y, q0 = blockIdx.x * 128;
    const int w = tid >> 5, lane = tid & 31;
    const int gid = lane >> 2, tig = lane & 3;
    const int wm = (w >> 1) * 32, wn = (w & 1) * 32;
    const int arow = tid >> 1, ak = (tid & 1) * 8;
    const int vrow = tid >> 4, vcol = (tid & 15) * 4;
    const float* Ap = alpha + (long long)bh * Ll * Ll + (long long)(q0 + arow) * Ll + ak;
    const float* Vp = vv + (long long)bh * Ll * DHh + (long long)vrow * DHh + vcol;

    float acc[2][4][4];
#pragma unroll
    for (int i = 0; i < 2; i++)
#pragma unroll
        for (int j = 0; j < 4; j++)
#pragma unroll
            for (int u = 0; u < 4; u++) acc[i][j][u] = 0.f;

    for (int k0 = 0; k0 < Ll; k0 += 16) {
        float4 a0 = *(const float4*)(Ap + k0);
        float4 a1 = *(const float4*)(Ap + k0 + 4);
        float4 v4 = *(const float4*)(Vp + (long long)k0 * DHh);
        __syncthreads();
        As[ak + 0][arow] = f2tf(a0.x); As[ak + 1][arow] = f2tf(a0.y);
        As[ak + 2][arow] = f2tf(a0.z); As[ak + 3][arow] = f2tf(a0.w);
        As[ak + 4][arow] = f2tf(a1.x); As[ak + 5][arow] = f2tf(a1.y);
        As[ak + 6][arow] = f2tf(a1.z); As[ak + 7][arow] = f2tf(a1.w);
        uint4 t;
        t.x = f2tf(v4.x); t.y = f2tf(v4.y); t.z = f2tf(v4.z); t.w = f2tf(v4.w);
        *(uint4*)&Bs[vrow][vcol] = t;
        __syncthreads();
#pragma unroll
        for (int kk = 0; kk < 16; kk += 8) {
            unsigned af[2][4];
#pragma unroll
            for (int mt = 0; mt < 2; mt++) {
                const int r = wm + mt * 16 + gid;
                af[mt][0] = As[kk + tig][r];
                af[mt][1] = As[kk + tig][r + 8];
                af[mt][2] = As[kk + tig + 4][r];
                af[mt][3] = As[kk + tig + 4][r + 8];
            }
#pragma unroll
            for (int nt = 0; nt < 4; nt++) {
                unsigned bf[2];
                const int c = wn + nt * 8 + gid;
                bf[0] = Bs[kk + tig][c];
                bf[1] = Bs[kk + tig + 4][c];
                mma_tf32(acc[0][nt], af[0], bf);
                mma_tf32(acc[1][nt], af[1], bf);
            }
        }
    }

    const int b = bh >> 4, h = bh & 15;
#pragma unroll
    for (int mt = 0; mt < 2; mt++) {
#pragma unroll
        for (int half = 0; half < 2; half++) {
            const int q = q0 + wm + mt * 16 + gid + half * 8;
#pragma unroll
            for (int nt = 0; nt < 4; nt++) {
                const int d = wn + nt * 8 + 2 * tig;
                float2 v2;
                v2.x = acc[mt][nt][half * 2 + 0];
                v2.y = acc[mt][nt][half * 2 + 1];
                *(float2*)(ctx + ((long long)(b * Ll + q)) * Dd + h * DHh + d) = v2;
            }
        }
    }
}

// ============================================================
// AR (tensor core, NN): ctx[b*L+q, h*64+d] += sum_k alpha[bh,q,k] rel_v[q,k,d]
// Per q: M=64(bh), N=64(d), K=1024. rel_v streamed once. 8 warps, tile 16x32.
// ============================================================
__global__ void __launch_bounds__(256, 2) ar_tc(
    const float* __restrict__ alpha, const float* __restrict__ relv,
    float* __restrict__ ctx)
{
    __shared__ unsigned As[32][72];   // [k][bh]
    __shared__ unsigned Bs[32][72];   // [k][d]
    const int tid = threadIdx.x;
    const int qp = blockIdx.x;
    const int w = tid >> 5, lane = tid & 31;
    const int gid = lane >> 2, tig = lane & 3;
    const int wm = (w >> 1) * 16, wn = (w & 1) * 32;
    const int arow = tid >> 2, ak = (tid & 3) * 8;
    const int brow = tid >> 3, bc = (tid & 7) * 8;
    const float* Ap = alpha + ((long long)arow * Ll + qp) * Ll + ak;
    const float* Rp = relv + ((long long)qp * Ll + brow) * DHh + bc;

    float acc[4][4];
#pragma unroll
    for (int j = 0; j < 4; j++)
#pragma unroll
        for (int u = 0; u < 4; u++) acc[j][u] = 0.f;

    for (int k0 = 0; k0 < Ll; k0 += 32) {
        float4 a0 = *(const float4*)(Ap + k0);
        float4 a1 = *(const float4*)(Ap + k0 + 4);
        float4 r0 = *(const float4*)(Rp + (long long)k0 * DHh);
        float4 r1 = *(const float4*)(Rp + (long long)k0 * DHh + 4);
        __syncthreads();
        As[ak + 0][arow] = f2tf(a0.x); As[ak + 1][arow] = f2tf(a0.y);
        As[ak + 2][arow] = f2tf(a0.z); As[ak + 3][arow] = f2tf(a0.w);
        As[ak + 4][arow] = f2tf(a1.x); As[ak + 5][arow] = f2tf(a1.y);
        As[ak + 6][arow] = f2tf(a1.z); As[ak + 7][arow] = f2tf(a1.w);
        uint4 t0, t1;
        t0.x = f2tf(r0.x); t0.y = f2tf(r0.y); t0.z = f2tf(r0.z); t0.w = f2tf(r0.w);
        t1.x = f2tf(r1.x); t1.y = f2tf(r1.y); t1.z = f2tf(r1.z); t1.w = f2tf(r1.w);
        *(uint4*)&Bs[brow][bc]     = t0;
        *(uint4*)&Bs[brow][bc + 4] = t1;
        __syncthreads();
#pragma unroll
        for (int kk = 0; kk < 32; kk += 8) {
            unsigned af[4];
            const int r = wm + gid;
            af[0] = As[kk + tig][r];
            af[1] = As[kk + tig][r + 8];
            af[2] = As[kk + tig + 4][r];
            af[3] = As[kk + tig + 4][r + 8];
#pragma unroll
            for (int nt = 0; nt < 4; nt++) {
                unsigned bf[2];
                const int c = wn + nt * 8 + gid;
                bf[0] = Bs[kk + tig][c];
                bf[1] = Bs[kk + tig + 4][c];
                mma_tf32(acc[nt], af, bf);
            }
        }
    }

#pragma unroll
    for (int half = 0; half < 2; half++) {
        const int bh = wm + gid + half * 8;
        const int b = bh >> 4, h = bh & 15;
#pragma unroll
        for (int nt = 0; nt < 4; nt++) {
            const int d = wn + nt * 8 + 2 * tig;
            float* Cp = ctx + ((long long)(b * Ll + qp)) * Dd + h * DHh + d;
            float2 c = *(float2*)Cp;
            c.x += acc[nt][half * 2 + 0];
            c.y += acc[nt][half * 2 + 1];
            *(float2*)Cp = c;
        }
    }
}

// ============================================================
extern "C" void kernel_launch(void* const* d_in, const int* in_sizes, int n_in,
                              void* d_out, int out_size)
{
    const float* key   = (const float*)d_in[0];
    const float* value = (const float*)d_in[1];
    const float* query = (const float*)d_in[2];
    const unsigned char* mask = (const unsigned char*)d_in[3];
    const float* rel_k = (const float*)d_in[4];
    const float* rel_v = (const float*)d_in[5];
    const float* Wk = (const float*)d_in[6];
    const float* bk = (const float*)d_in[7];
    const float* Wv = (const float*)d_in[8];
    const float* bv = (const float*)d_in[9];
    const float* Wq = (const float*)d_in[10];
    const float* bq = (const float*)d_in[11];
    const float* Wo = (const float*)d_in[12];
    const float* bo = (const float*)d_in[13];
    float* out = (float*)d_out;

    float *pq, *pk, *pv, *plog, *pctx;
    cudaGetSymbolAddress((void**)&pq,   g_q);
    cudaGetSymbolAddress((void**)&pk,   g_k);
    cudaGetSymbolAddress((void**)&pv,   g_v);
    cudaGetSymbolAddress((void**)&plog, g_logits);
    cudaGetSymbolAddress((void**)&pctx, g_ctx);

    dim3 blk(256);

    // Q/K/V projections: [4096,1024] x [1024,1024]^T, split-head output.
    gemm_nt_tc<<<dim3(8, 32, 1), blk>>>(query, Wq, bq, pq, 1024, 0, 0, 0, 0.125f, 1);
    gemm_nt_tc<<<dim3(8, 32, 1), blk>>>(key,   Wk, bk, pk, 1024, 0, 0, 0, 1.0f,   1);
    gemm_nt_tc<<<dim3(8, 32, 1), blk>>>(value, Wv, bv, pv, 1024, 0, 0, 0, 1.0f,   1);

    // QK logits: batched over bh, K=64.
    gemm_nt_tc<<<dim3(8, 8, 64), blk>>>(pq, pk, nullptr, plog, 64,
        (long long)Ll * DHh, (long long)Ll * DHh, (long long)Ll * Ll, 1.0f, 0);

    // += relative-key score (rel_k streamed once).
    qr_tc<<<dim3(8, 1024), blk>>>(pq, rel_k, plog);

    // masked softmax in place.
    softmax_kernel<<<dim3(1024, 64), blk>>>(plog, mask);

    // alpha @ V -> ctx
    av_tc<<<dim3(8, 64), blk>>>(plog, pv, pctx);

    // ctx += alpha @ rel_v (rel_v streamed once).
    ar_tc<<<dim3(1024, 1, 1), blk>>>(plog, rel_v, pctx);

    // output projection.
    gemm_nt_tc<<<dim3(8, 32, 1), blk>>>(pctx, Wo, bo, out, 1024, 0, 0, 0, 1.0f, 0);
}